// round 17
// baseline (speedup 1.0000x reference)
#include <cuda_runtime.h>
#include <cuda_bf16.h>

#define NCLS 10
#define DIM  128
#define WARPS_PER_BLOCK 4
#define BLOCK_THREADS   (WARPS_PER_BLOCK * 32)
#define GRID_BLOCKS     740   // 148 SMs * 5 blocks (R2 residency)

// Global scratch (allocation-free), zeroed every launch -> deterministic replay.
__device__ float        g_sum[NCLS * DIM];
__device__ float        g_q[NCLS];          // per-class total sum-of-squares
__device__ unsigned int g_cnt[NCLS];

__global__ void CLIR_zero_kernel() {
    int i = blockIdx.x * blockDim.x + threadIdx.x;
    if (i < NCLS * DIM) g_sum[i] = 0.0f;
    if (i < NCLS) { g_q[i] = 0.0f; g_cnt[i] = 0u; }
}

// ---------------------------------------------------------------------------
// R2 structure with ONE change: the sum-of-squares accumulator moves from a
// float4 smem RMW into 10 PREDICATED REGISTERS (q_c += (c==n) ? d : 0, FSEL+
// FADD, branch-free). Hot-loop smem traffic halves: only the sum's
// LDS.128+STS.128 remain -> 16 cyc/row/SM crossbar vs R2's 32. Avoids the
// banned scalar smem RMW (R15: 391us) and the branch-tree switch (R6).
// One warp = one row/iter; per-warp private sum copies -> no hot-loop races.
// ---------------------------------------------------------------------------
__global__ __launch_bounds__(BLOCK_THREADS)
void CLIR_accum_kernel(const float* __restrict__ x,
                       const int*   __restrict__ t,
                       int N) {
    __shared__ float s_sum[WARPS_PER_BLOCK][NCLS * DIM];   // 20 KB
    __shared__ float s_pad[WARPS_PER_BLOCK][NCLS * DIM];   // 20 KB pad: pin 5 blk/SM
    __shared__ unsigned int s_cnt[NCLS];

    const int tid  = threadIdx.x;
    const int lane = tid & 31;
    const int w    = tid >> 5;

    float* s_sum_flat = &s_sum[0][0];
    for (int i = tid; i < WARPS_PER_BLOCK * NCLS * DIM; i += BLOCK_THREADS)
        s_sum_flat[i] = 0.0f;
    if (tid < NCLS) s_cnt[tid] = 0u;
    // touch pad so it is not elided
    if (tid == 0) s_pad[0][0] = 0.0f;
    __syncthreads();

    float* ms = s_sum[w];
    const float4* __restrict__ x4 = (const float4*)x;

    float q0 = 0.f, q1 = 0.f, q2 = 0.f, q3 = 0.f, q4 = 0.f;
    float q5 = 0.f, q6 = 0.f, q7 = 0.f, q8 = 0.f, q9 = 0.f;

    for (int row = blockIdx.x * WARPS_PER_BLOCK + w; row < N;
         row += GRID_BLOCKS * WARPS_PER_BLOCK) {
        const int c = __ldg(&t[row]);                        // warp-uniform
        const float4 v = x4[(size_t)row * (DIM / 4) + lane]; // 512B/warp coalesced

        float4* ps = (float4*)(ms + c * DIM + lane * 4);
        float4 a = *ps;
        a.x += v.x; a.y += v.y; a.z += v.z; a.w += v.w;
        *ps = a;

        const float d = fmaf(v.y, v.y, v.x * v.x)
                      + fmaf(v.w, v.w, v.z * v.z);
        q0 += (c == 0) ? d : 0.0f;
        q1 += (c == 1) ? d : 0.0f;
        q2 += (c == 2) ? d : 0.0f;
        q3 += (c == 3) ? d : 0.0f;
        q4 += (c == 4) ? d : 0.0f;
        q5 += (c == 5) ? d : 0.0f;
        q6 += (c == 6) ? d : 0.0f;
        q7 += (c == 7) ? d : 0.0f;
        q8 += (c == 8) ? d : 0.0f;
        q9 += (c == 9) ? d : 0.0f;

        if (lane == 0) atomicAdd(&s_cnt[c], 1u);
    }
    __syncthreads();

    // Fold the 4 warp sum-copies -> spread global float atomics (R2 epilogue).
    for (int i = tid; i < NCLS * DIM; i += BLOCK_THREADS) {
        const float vs = s_sum[0][i] + s_sum[1][i] + s_sum[2][i] + s_sum[3][i];
        atomicAdd(&g_sum[i], vs);
    }

    // q registers: shuffle-reduce per warp, lane0 REDG per class.
    #define QRED(n, qn) do {                                            \
        float v_ = qn;                                                  \
        for (int o_ = 16; o_ > 0; o_ >>= 1)                             \
            v_ += __shfl_xor_sync(0xFFFFFFFFu, v_, o_);                 \
        if (lane == 0) atomicAdd(&g_q[n], v_);                          \
    } while (0)
    QRED(0, q0); QRED(1, q1); QRED(2, q2); QRED(3, q3); QRED(4, q4);
    QRED(5, q5); QRED(6, q6); QRED(7, q7); QRED(8, q8); QRED(9, q9);
    #undef QRED

    if (tid < NCLS) atomicAdd(&g_cnt[tid], s_cnt[tid]);
}

// ---------------------------------------------------------------------------
// penalty = (1/C) * Sum_c [ q_c/(n_c-1) - Sum_d sum[c][d]^2 / (n_c (n_c-1)) ]
// (same math as R14/R15 finalize, verified at rel_err ~1.6e-5)
// ---------------------------------------------------------------------------
__global__ void CLIR_finalize_kernel(float* __restrict__ out) {
    __shared__ float scnt[NCLS];
    const int d = threadIdx.x;   // 128 threads
    if (d < NCLS) scnt[d] = (float)g_cnt[d];
    __syncthreads();

    float p = 0.0f;
    #pragma unroll
    for (int c = 0; c < NCLS; c++) {
        const float n = scnt[c];
        const float s = g_sum[c * DIM + d];
        p += (s * s) / (n * (n - 1.0f));
    }
    #pragma unroll
    for (int o = 16; o > 0; o >>= 1)
        p += __shfl_xor_sync(0xFFFFFFFFu, p, o);
    __shared__ float wr[4];
    if ((d & 31) == 0) wr[d >> 5] = p;
    __syncthreads();
    if (d == 0) {
        float tr = 0.0f;
        #pragma unroll
        for (int c = 0; c < NCLS; c++)
            tr += g_q[c] / (scnt[c] - 1.0f);
        out[0] = (tr - (wr[0] + wr[1] + wr[2] + wr[3])) * (1.0f / (float)NCLS);
    }
}

extern "C" void kernel_launch(void* const* d_in, const int* in_sizes, int n_in,
                              void* d_out, int out_size) {
    const float* x = (const float*)d_in[0];
    const int*   t = (const int*)d_in[1];
    const int N = in_sizes[1];

    CLIR_zero_kernel<<<(NCLS * DIM + 255) / 256, 256>>>();
    CLIR_accum_kernel<<<GRID_BLOCKS, BLOCK_THREADS>>>(x, t, N);
    CLIR_finalize_kernel<<<1, DIM>>>((float*)d_out);
}